// round 17
// baseline (speedup 1.0000x reference)
#include <cuda_runtime.h>
#include <cuda_bf16.h>
#include <cstdint>
#include <math.h>

typedef unsigned long long u64;

#define L_   256
#define B_   128
#define D_   256
#define H_   256
#define NCOL 2048
#define HALF 16777216

// rec smem layout (float offsets)
#define F_W      0           // W64: [128 kp][128 col] u64           = 131072 B
#define F_H      32768       // h: [2 wg][32 row][256] fp32          = 65536 B
#define F_G      49152       // gates: [2 wg][32][128] fp32          = 32768 B
#define F_OFF    57344
#define F_LP     57602
#define F_PAR2   57666
#define DYN_SMEM 230920

__device__ float g_wx[(size_t)NCOL * D_];
__device__ float g_bias[NCOL];
__device__ float g_xi[(size_t)L_ * B_ * NCOL];
__device__ float g_acc_c[(size_t)B_ * 257 * H_];
__device__ float g_acc_h[(size_t)B_ * 257 * H_];
__device__ float g_td_h[(size_t)L_ * B_ * H_];
__device__ float g_td_c[(size_t)L_ * B_ * H_];
__device__ int   g_rankbuf[2 * 128 * 256];
__device__ int   g_wl[16 * 4096];
__device__ int   g_offs[16 * 258];
__device__ int   g_nrounds[16];

__device__ __forceinline__ void fma2(u64& c, u64 a, u64 b) {
    asm("fma.rn.f32x2 %0, %1, %2, %3;" : "=l"(c) : "l"(a), "l"(b), "l"(c));
}
__device__ __forceinline__ float2 up2(u64 v) {
    float2 f; asm("mov.b64 {%0, %1}, %2;" : "=f"(f.x), "=f"(f.y) : "l"(v)); return f;
}
__device__ __forceinline__ float sigm(float x) { return 1.0f / (1.0f + __expf(-x)); }
__device__ __forceinline__ void wgbar(int wg) {
    asm volatile("bar.sync %0, 256;" :: "r"(wg + 1) : "memory");
}

__global__ void rank_kernel(const int* __restrict__ parents) {
    int tid = threadIdx.x;
    int dir = tid >> 7, b = tid & 127;
    int rr[256];
    if (dir) {
        rr[0] = 0;
        for (int i = 1; i < 256; i++) rr[i] = rr[parents[i * B_ + b]] + 1;
    } else {
        for (int i = 0; i < 256; i++) rr[i] = 0;
        for (int i = 255; i >= 1; i--) {
            int p = parents[i * B_ + b];
            int v = rr[i] + 1;
            if (rr[p] < v) rr[p] = v;
        }
    }
    for (int i = 0; i < 256; i++) g_rankbuf[(dir * 128 + b) * 256 + i] = rr[i];
}

__global__ void wlist_kernel() {
    __shared__ int cnt[258], pos[258];
    __shared__ int maxr;
    int cl = blockIdx.x;
    int dir = cl >> 3, bg = cl & 7;
    int t = threadIdx.x;
    for (int i = t; i < 258; i += 256) cnt[i] = 0;
    if (t == 0) maxr = 0;
    __syncthreads();
    for (int idx = t; idx < 4096; idx += 256) {
        int bl = idx >> 8, n = idx & 255;
        int rk = g_rankbuf[(dir * 128 + bg * 16 + bl) * 256 + n];
        atomicAdd(&cnt[rk], 1);
        atomicMax(&maxr, rk);
    }
    __syncthreads();
    if (t == 0) {
        int acc = 0;
        for (int i = 0; i <= maxr + 1; i++) {
            pos[i] = acc;
            g_offs[cl * 258 + i] = acc;
            acc += cnt[i];
        }
        g_nrounds[cl] = maxr + 1;
    }
    __syncthreads();
    for (int idx = t; idx < 4096; idx += 256) {
        int bl = idx >> 8, n = idx & 255;
        int rk = g_rankbuf[(dir * 128 + bg * 16 + bl) * 256 + n];
        int p = atomicAdd(&pos[rk], 1);
        g_wl[cl * 4096 + p] = (bl << 8) | n;
    }
}

__global__ void pack_wx_kernel(const float* __restrict__ ioux_w, const float* __restrict__ ioux_b,
                               const float* __restrict__ iouh_b, const float* __restrict__ fx_w,
                               const float* __restrict__ fx_b, const float* __restrict__ fh_b,
                               int base) {
    int c = blockIdx.x;
    int k = threadIdx.x;
    const float* src = (c < 768) ? (ioux_w + (size_t)c * D_) : (fx_w + (size_t)(c - 768) * D_);
    g_wx[(size_t)(base + c) * D_ + k] = src[k];
    if (k == 0)
        g_bias[base + c] = (c < 768) ? (ioux_b[c] + iouh_b[c]) : (fx_b[c - 768] + fh_b[c - 768]);
}

// xgemm: CTA tile 64 rows x 128 cols, 8 warps of 32x32 full-K; lane 8 rows x 4 strided cols.
__global__ __launch_bounds__(256) void xgemm_kernel(const float* __restrict__ A) {
    __shared__ float As[64 * 36];      // [row][k]
    __shared__ u64 Bs[16 * 128];       // [kp][col]
    float* Bsf = (float*)Bs;
    int mBase = blockIdx.x * 64;
    int nBase = blockIdx.y * 128;
    int t = threadIdx.x;
    int lane = t & 31;
    int w = t >> 5;
    const int mq = w >> 2, nq = w & 3;
    const int a = lane >> 3, b = lane & 7;
    const int lm = t >> 2, lk = (t & 3) * 8;
    const int cn = t & 127, kr = (t >> 7) * 16;

    u64 acc[8][4];
#pragma unroll
    for (int i = 0; i < 8; i++)
#pragma unroll
        for (int s = 0; s < 4; s++) acc[i][s] = 0ull;

    for (int kt = 0; kt < 256; kt += 32) {
        __syncthreads();
        {
            const float* ap = A + (size_t)(mBase + lm) * D_ + kt + lk;
            *(float4*)(As + lm * 36 + lk) = *(const float4*)(ap);
            *(float4*)(As + lm * 36 + lk + 4) = *(const float4*)(ap + 4);
        }
        {
            const float* wp = g_wx + (size_t)(nBase + cn) * D_ + kt + kr;
#pragma unroll
            for (int q = 0; q < 4; q++) {
                float4 bv = *(const float4*)(wp + q * 4);
                float v[4] = {bv.x, bv.y, bv.z, bv.w};
#pragma unroll
                for (int e = 0; e < 4; e++) {
                    int kk = kr + q * 4 + e;
                    Bsf[((kk >> 1) * 128 + cn) * 2 + (kk & 1)] = v[e];
                }
            }
        }
        __syncthreads();
        const float* hb = As + (mq * 32 + 8 * a) * 36;
#pragma unroll
        for (int kq = 0; kq < 8; kq++) {
            u64 w0[4], w1[4];
#pragma unroll
            for (int s = 0; s < 4; s++) {
                w0[s] = Bs[(2 * kq) * 128 + nq * 32 + b + 8 * s];
                w1[s] = Bs[(2 * kq + 1) * 128 + nq * 32 + b + 8 * s];
            }
#pragma unroll
            for (int i = 0; i < 8; i++) {
                ulonglong2 hv = *(const ulonglong2*)(hb + i * 36 + kq * 4);
#pragma unroll
                for (int s = 0; s < 4; s++) {
                    fma2(acc[i][s], hv.x, w0[s]);
                    fma2(acc[i][s], hv.y, w1[s]);
                }
            }
        }
    }
#pragma unroll
    for (int i = 0; i < 8; i++)
#pragma unroll
        for (int s = 0; s < 4; s++) {
            float2 e = up2(acc[i][s]);
            int col = nBase + nq * 32 + b + 8 * s;
            g_xi[(size_t)(mBase + mq * 32 + 8 * a + i) * NCOL + col] =
                e.x + e.y + g_bias[col];
        }
}

// rec: 2 wg x 32-row chunks; 8 warps/wg = khalf(2) x colquarter(4); warp 32 rows x 32 cols;
// lane 8 rows x 4 strided cols. K-halves merged via two-phase gate store/add.
__global__ __launch_bounds__(512, 1) __cluster_dims__(8, 1, 1)
void rec_kernel(const int* __restrict__ parents,
                const float* __restrict__ dt_iouh_w, const float* __restrict__ dt_fh_w,
                const float* __restrict__ td_iouh_w, const float* __restrict__ td_fh_w,
                float* __restrict__ out) {
    extern __shared__ float smem[];
    float* Wf      = smem + F_W;
    u64*   W64     = (u64*)(smem + F_W);
    float* h_s     = smem + F_H;
    float* gates_s = smem + F_G;
    int*   off_s   = (int*)(smem + F_OFF);
    int*   lp_s    = (int*)(smem + F_LP);
    int*   pp_s    = (int*)(smem + F_PAR2);

    const int blk = blockIdx.x;
    const int r   = blk & 7;
    const int cid = blk >> 3;
    const int dir = cid >> 3;
    const int bg  = cid & 7;
    const int t   = threadIdx.x;
    const int lane = t & 31;
    const int wg   = t >> 8;
    const int t256 = t & 255;
    const int w8   = t256 >> 5;

    const float* iouh = dir ? td_iouh_w : dt_iouh_w;
    const float* fh   = dir ? td_fh_w : dt_fh_w;

    // Wh slice -> [kp][col] u64
    {
        int cc = t & 127;
        int g = cc >> 5, j = cc & 31;
        const float* src = (g < 3) ? (iouh + (size_t)(g * 256 + r * 32 + j) * H_)
                                   : (fh + (size_t)(r * 32 + j) * H_);
        int k0 = (t >> 7) * 64;
        for (int k = k0; k < k0 + 64; k++)
            Wf[((k >> 1) * 128 + cc) * 2 + (k & 1)] = src[k];
    }
    for (int i = t; i < 258; i += 512) off_s[i] = g_offs[cid * 258 + i];
    const int nR = g_nrounds[cid];
    __syncthreads();

    const int khalf = w8 >> 2;
    const int cq4   = w8 & 3;
    const int a     = lane >> 3;
    const int b     = lane & 7;
    const int cwb   = cq4 * 32;
    const int erow = t256 >> 3;
    const int ejj  = (t256 & 7) * 4;

    float* myh   = h_s + wg * 8192;
    float* myg   = gates_s + wg * 32 * 128;
    int*   mylp  = lp_s + wg * 32;
    int*   mypp  = pp_s + wg * 32;

    for (int rd = 0; rd < nR; rd++) {
        const int base = off_s[rd];
        const int end  = off_s[rd + 1];
        const int C32 = (end - base + 31) >> 5;

        for (int ci = wg; ci < C32; ci += 2) {
            if (t256 < 32) {
                int ridx = base + ci * 32 + t256;
                int pair = (ridx < end) ? __ldg(&g_wl[cid * 4096 + ridx]) : -1;
                mylp[t256] = pair;
                mypp[t256] = (pair >= 0)
                    ? __ldg(&parents[(pair & 255) * B_ + bg * 16 + (pair >> 8)]) : 0;
            }
            wgbar(wg);

            // gather h: warp w8 -> rows w8*4..+3
#pragma unroll
            for (int q = 0; q < 4; q++) {
                int row = w8 * 4 + q;
                int pair = mylp[row];
                float4 z = make_float4(0.f, 0.f, 0.f, 0.f);
                const float* hsrc = nullptr;
                bool zero = true;
                if (pair >= 0) {
                    int bl = pair >> 8, n = pair & 255;
                    int bb = bg * 16 + bl;
                    int p = mypp[row];
                    if (dir) {
                        if (p != 256) { hsrc = g_td_h + ((size_t)p * B_ + bb) * 256; zero = false; }
                    } else {
                        hsrc = g_acc_h + ((size_t)bb * 257 + n) * 256; zero = false;
                    }
                }
                float4 v0 = zero ? z : __ldcg((const float4*)(hsrc + lane * 4));
                float4 v1 = zero ? z : __ldcg((const float4*)(hsrc + 128 + lane * 4));
                *(float4*)(myh + row * 256 + lane * 4) = v0;
                *(float4*)(myh + row * 256 + 128 + lane * 4) = v1;
            }
            float4 exi0, exi1, exi2, exi3, esc;
            exi0 = exi1 = exi2 = exi3 = esc = make_float4(0.f, 0.f, 0.f, 0.f);
            {
                int pair = mylp[erow];
                if (pair >= 0) {
                    int bl = pair >> 8, n = pair & 255;
                    int bb = bg * 16 + bl;
                    int p = mypp[erow];
                    const float* xb = g_xi + ((size_t)n * B_ + bb) * NCOL + dir * 1024 + r * 32 + ejj;
                    exi0 = __ldcg((const float4*)(xb));
                    exi1 = __ldcg((const float4*)(xb + 256));
                    exi2 = __ldcg((const float4*)(xb + 512));
                    exi3 = __ldcg((const float4*)(xb + 768));
                    if (dir) {
                        if (p != 256)
                            esc = __ldcg((const float4*)(g_td_c + ((size_t)p * B_ + bb) * 256 + r * 32 + ejj));
                    } else {
                        esc = __ldcg((const float4*)(g_acc_c + ((size_t)bb * 257 + n) * 256 + r * 32 + ejj));
                    }
                }
            }
            wgbar(wg);

            // GEMM: 8 rows x 4 strided cols per lane over this khalf's 128 k
            u64 acc[8][4];
#pragma unroll
            for (int i = 0; i < 8; i++)
#pragma unroll
                for (int s = 0; s < 4; s++) acc[i][s] = 0ull;
            {
                const float* hb = myh + 8 * a * 256 + khalf * 128;
                const int kp00 = khalf * 64;
#pragma unroll 4
                for (int kq = 0; kq < 32; kq++) {
                    u64 w0[4], w1[4];
#pragma unroll
                    for (int s = 0; s < 4; s++) {
                        w0[s] = W64[(kp00 + 2 * kq) * 128 + cwb + b + 8 * s];
                        w1[s] = W64[(kp00 + 2 * kq + 1) * 128 + cwb + b + 8 * s];
                    }
#pragma unroll
                    for (int i = 0; i < 8; i++) {
                        ulonglong2 hv = *(const ulonglong2*)(hb + i * 256 + kq * 4);
#pragma unroll
                        for (int s = 0; s < 4; s++) {
                            fma2(acc[i][s], hv.x, w0[s]);
                            fma2(acc[i][s], hv.y, w1[s]);
                        }
                    }
                }
            }
            float v[8][4];
#pragma unroll
            for (int i = 0; i < 8; i++)
#pragma unroll
                for (int s = 0; s < 4; s++) {
                    float2 e = up2(acc[i][s]);
                    v[i][s] = e.x + e.y;
                }
            if (khalf == 0) {
#pragma unroll
                for (int i = 0; i < 8; i++)
#pragma unroll
                    for (int s = 0; s < 4; s++)
                        myg[(8 * a + i) * 128 + cwb + b + 8 * s] = v[i][s];
            }
            wgbar(wg);
            if (khalf == 1) {
#pragma unroll
                for (int i = 0; i < 8; i++)
#pragma unroll
                    for (int s = 0; s < 4; s++)
                        myg[(8 * a + i) * 128 + cwb + b + 8 * s] += v[i][s];
            }
            wgbar(wg);

            // epilogue
            {
                int pair = mylp[erow];
                if (pair >= 0) {
                    int bl = pair >> 8, n = pair & 255;
                    int bb = bg * 16 + bl;
                    int p = mypp[erow];
                    float4 gi = *(const float4*)(myg + erow * 128 + ejj);
                    float4 go = *(const float4*)(myg + erow * 128 + 32 + ejj);
                    float4 gu = *(const float4*)(myg + erow * 128 + 64 + ejj);
                    float4 gf = *(const float4*)(myg + erow * 128 + 96 + ejj);
                    float ii[4] = {gi.x + exi0.x, gi.y + exi0.y, gi.z + exi0.z, gi.w + exi0.w};
                    float oo[4] = {go.x + exi1.x, go.y + exi1.y, go.z + exi1.z, go.w + exi1.w};
                    float uu[4] = {gu.x + exi2.x, gu.y + exi2.y, gu.z + exi2.z, gu.w + exi2.w};
                    float ff[4] = {gf.x + exi3.x, gf.y + exi3.y, gf.z + exi3.z, gf.w + exi3.w};
                    float scv[4] = {esc.x, esc.y, esc.z, esc.w};
                    float cv[4], hv[4];
#pragma unroll
                    for (int d = 0; d < 4; d++) {
                        float ig = sigm(ii[d]);
                        float og = sigm(oo[d]);
                        float ug = tanhf(uu[d]);
                        float fg = sigm(ff[d]);
                        cv[d] = ig * ug + fg * scv[d];
                        hv[d] = og * tanhf(cv[d]);
                    }
                    float4 cf = make_float4(cv[0], cv[1], cv[2], cv[3]);
                    float4 hf = make_float4(hv[0], hv[1], hv[2], hv[3]);
                    size_t orow = ((size_t)n * B_ + bb) * 512 + (size_t)dir * 256 + r * 32 + ejj;
                    __stcg((float4*)(out + orow), cf);
                    __stcg((float4*)(out + HALF + orow), hf);
                    if (dir) {
                        size_t trow = ((size_t)n * B_ + bb) * 256 + r * 32 + ejj;
                        __stcg((float4*)(g_td_h + trow), hf);
                        __stcg((float4*)(g_td_c + trow), cf);
                    } else {
                        size_t arow = ((size_t)bb * 257 + p) * 256 + r * 32 + ejj;
#pragma unroll
                        for (int d = 0; d < 4; d++) {
                            atomicAdd(&g_acc_h[arow + d], hv[d]);
                            atomicAdd(&g_acc_c[arow + d], cv[d]);
                        }
                    }
                }
            }
            wgbar(wg);
        }

        __syncthreads();
        asm volatile("barrier.cluster.arrive.aligned;" ::: "memory");
        asm volatile("barrier.cluster.wait.aligned;" ::: "memory");
    }
}

extern "C" void kernel_launch(void* const* d_in, const int* in_sizes, int n_in,
                              void* d_out, int out_size) {
    const float* inputs = (const float*)d_in[0];
    const int* parents = (const int*)d_in[2];

    rank_kernel<<<1, 256>>>(parents);
    wlist_kernel<<<16, 256>>>();

    pack_wx_kernel<<<1024, 256>>>((const float*)d_in[3], (const float*)d_in[4],
                                  (const float*)d_in[6], (const float*)d_in[7],
                                  (const float*)d_in[8], (const float*)d_in[10], 0);
    pack_wx_kernel<<<1024, 256>>>((const float*)d_in[11], (const float*)d_in[12],
                                  (const float*)d_in[14], (const float*)d_in[15],
                                  (const float*)d_in[16], (const float*)d_in[18], 1024);

    dim3 gg(512, 16);
    xgemm_kernel<<<gg, 256>>>(inputs);

    void* accc = nullptr; void* acch = nullptr;
    cudaGetSymbolAddress(&accc, g_acc_c);
    cudaGetSymbolAddress(&acch, g_acc_h);
    cudaMemsetAsync(accc, 0, sizeof(float) * (size_t)B_ * 257 * H_);
    cudaMemsetAsync(acch, 0, sizeof(float) * (size_t)B_ * 257 * H_);

    cudaFuncSetAttribute(rec_kernel, cudaFuncAttributeMaxDynamicSharedMemorySize, DYN_SMEM);
    rec_kernel<<<128, 512, DYN_SMEM>>>(parents,
                                       (const float*)d_in[5], (const float*)d_in[9],
                                       (const float*)d_in[13], (const float*)d_in[17],
                                       (float*)d_out);
}